// round 9
// baseline (speedup 1.0000x reference)
#include <cuda_runtime.h>
#include <math.h>

#define Bsz 4
#define Tt  4096
#define Cc  1024
#define Hh  64
#define BT  (Bsz*Tt)

// q,k: [token][32] u32 (bf16x2 over h-pairs).
// v: [batch][h=64][tp=2048] u32, u16 lo = even token, hi = odd token.
// q pre-scaled by C^-0.5 = 1/32.
__device__ unsigned g_qh[BT*32];
__device__ unsigned g_ql[BT*32];
__device__ unsigned g_kh[BT*32];
__device__ unsigned g_kl[BT*32];
__device__ unsigned g_vh[BT*32];
__device__ unsigned g_vl[BT*32];

// split-KV partials
__device__ float g_op[2][BT*64];
__device__ float g_m[2][BT];
__device__ float g_l[2][BT];

// ---------------------------------------------------------------------------
// helpers
// ---------------------------------------------------------------------------
__device__ __forceinline__ void mma16816(float c[4], unsigned a0, unsigned a1,
                                         unsigned a2, unsigned a3,
                                         unsigned b0, unsigned b1) {
    asm volatile(
        "mma.sync.aligned.m16n8k16.row.col.f32.bf16.bf16.f32 "
        "{%0,%1,%2,%3}, {%4,%5,%6,%7}, {%8,%9}, {%0,%1,%2,%3};\n"
        : "+f"(c[0]), "+f"(c[1]), "+f"(c[2]), "+f"(c[3])
        : "r"(a0), "r"(a1), "r"(a2), "r"(a3), "r"(b0), "r"(b1));
}
__device__ __forceinline__ void ldsm4(unsigned r[4], unsigned addr) {
    asm volatile("ldmatrix.sync.aligned.m8n8.x4.shared.b16 {%0,%1,%2,%3}, [%4];"
                 : "=r"(r[0]), "=r"(r[1]), "=r"(r[2]), "=r"(r[3]) : "r"(addr));
}
__device__ __forceinline__ unsigned pack_hi(float x, float y) {
    return (__float_as_uint(x) >> 16) | (__float_as_uint(y) & 0xFFFF0000u);
}
__device__ __forceinline__ float trunc_bf(float x) {
    return __uint_as_float(__float_as_uint(x) & 0xFFFF0000u);
}
__device__ __forceinline__ unsigned pack_rn(float x, float y) {
    unsigned r;
    asm("cvt.rn.bf16x2.f32 %0, %1, %2;" : "=r"(r) : "f"(y), "f"(x));
    return r;
}
__device__ __forceinline__ void cpa16(unsigned dst, const void* src) {
    asm volatile("cp.async.cg.shared.global [%0], [%1], 16;\n"
                 :: "r"(dst), "l"(src));
}
#define CP_COMMIT() asm volatile("cp.async.commit_group;\n" ::: "memory")
#define CP_WAIT(n)  asm volatile("cp.async.wait_group %0;\n" :: "n"(n) : "memory")

// ---------------------------------------------------------------------------
// Kernel 1: FUSED QKV projection, ldmatrix fragment loads.
// CTA: 128 thr / 4 warps, tile M=64, N=64 (x3 outputs), K-chunk 16.
// X smem: [row][k-pair] stride 12.  W smem: [n][k-pair] stride 20.
// ---------------------------------------------------------------------------
__global__ __launch_bounds__(128) void qkv_gemm(const float* __restrict__ x,
                                                const float* __restrict__ Wq,
                                                const float* __restrict__ Wk,
                                                const float* __restrict__ Wv) {
    __shared__ unsigned Xh[64][12], Xl[64][12];
    __shared__ unsigned Wp2h[3][64][20], Wp2l[3][64][20];

    const int m0   = blockIdx.x * 64;
    const int tid  = threadIdx.x;
    const int w    = tid >> 5;
    const int lane = tid & 31;
    const int gid  = lane >> 2;
    const int tig  = lane & 3;

    const int xrow = tid >> 1;            // 0..63
    const int xkq  = (tid & 1) << 1;      // float4 group 0 or 2
    const int wkk  = tid >> 4;            // k-pair 0..7
    const int wn2  = tid & 15;            // n base; rows wn2 + 16jj

    const float* __restrict__ Ws[3] = {Wq, Wk, Wv};

    // ldmatrix per-thread offsets (bytes)
    const unsigned xh_base = (unsigned)__cvta_generic_to_shared(Xh);
    const unsigned xl_base = (unsigned)__cvta_generic_to_shared(Xl);
    const unsigned a_off = ((w * 16 + ((lane >> 3) & 1) * 8 + (lane & 7)) * 12
                            + (lane >> 4) * 4) * 4;
    const unsigned w_off = ((8 * (lane >> 4) + (lane & 7)) * 20
                            + ((lane >> 3) & 1) * 4) * 4;

    float acc[3][8][4];
    #pragma unroll
    for (int q = 0; q < 3; q++)
        #pragma unroll
        for (int j = 0; j < 8; j++)
            #pragma unroll
            for (int e = 0; e < 4; e++) acc[q][j][e] = 0.f;

    // prefetch chunk 0
    float4 xa = *(const float4*)&x[(size_t)(m0 + xrow) * Cc + xkq * 4];
    float4 xb = *(const float4*)&x[(size_t)(m0 + xrow) * Cc + (xkq + 1) * 4];
    float wa[3][4], wb[3][4];
    #pragma unroll
    for (int q = 0; q < 3; q++)
        #pragma unroll
        for (int jj = 0; jj < 4; jj++) {
            wa[q][jj] = Ws[q][(size_t)(2 * wkk) * Hh + wn2 + 16 * jj];
            wb[q][jj] = Ws[q][(size_t)(2 * wkk + 1) * Hh + wn2 + 16 * jj];
        }

    for (int c = 0; c < 64; c++) {
        Xh[xrow][2 * xkq + 0] = pack_hi(xa.x, xa.y);
        Xh[xrow][2 * xkq + 1] = pack_hi(xa.z, xa.w);
        Xl[xrow][2 * xkq + 0] = pack_rn(xa.x - trunc_bf(xa.x), xa.y - trunc_bf(xa.y));
        Xl[xrow][2 * xkq + 1] = pack_rn(xa.z - trunc_bf(xa.z), xa.w - trunc_bf(xa.w));
        Xh[xrow][2 * xkq + 2] = pack_hi(xb.x, xb.y);
        Xh[xrow][2 * xkq + 3] = pack_hi(xb.z, xb.w);
        Xl[xrow][2 * xkq + 2] = pack_rn(xb.x - trunc_bf(xb.x), xb.y - trunc_bf(xb.y));
        Xl[xrow][2 * xkq + 3] = pack_rn(xb.z - trunc_bf(xb.z), xb.w - trunc_bf(xb.w));
        #pragma unroll
        for (int q = 0; q < 3; q++)
            #pragma unroll
            for (int jj = 0; jj < 4; jj++) {
                float a = wa[q][jj], b = wb[q][jj];
                Wp2h[q][wn2 + 16 * jj][wkk] = pack_hi(a, b);
                Wp2l[q][wn2 + 16 * jj][wkk] =
                    pack_rn(a - trunc_bf(a), b - trunc_bf(b));
            }
        __syncthreads();

        if (c < 63) {
            int k0 = (c + 1) * 16;
            xa = *(const float4*)&x[(size_t)(m0 + xrow) * Cc + k0 + xkq * 4];
            xb = *(const float4*)&x[(size_t)(m0 + xrow) * Cc + k0 + (xkq + 1) * 4];
            #pragma unroll
            for (int q = 0; q < 3; q++)
                #pragma unroll
                for (int jj = 0; jj < 4; jj++) {
                    wa[q][jj] = Ws[q][(size_t)(k0 + 2 * wkk) * Hh + wn2 + 16 * jj];
                    wb[q][jj] = Ws[q][(size_t)(k0 + 2 * wkk + 1) * Hh + wn2 + 16 * jj];
                }
        }

        unsigned A4h[4], A4l[4];
        ldsm4(A4h, xh_base + a_off);
        ldsm4(A4l, xl_base + a_off);

        #pragma unroll
        for (int q = 0; q < 3; q++) {
            const unsigned wh_base =
                (unsigned)__cvta_generic_to_shared(Wp2h[q]) + w_off;
            const unsigned wl_base =
                (unsigned)__cvta_generic_to_shared(Wp2l[q]) + w_off;
            #pragma unroll
            for (int J = 0; J < 8; J += 2) {
                unsigned B4h[4], B4l[4];
                ldsm4(B4h, wh_base + J * 640);
                ldsm4(B4l, wl_base + J * 640);
                #pragma unroll
                for (int d = 0; d < 2; d++) {
                    int jn = J + d;
                    mma16816(acc[q][jn], A4h[0], A4h[1], A4h[2], A4h[3],
                             B4h[2 * d], B4h[2 * d + 1]);
                    mma16816(acc[q][jn], A4l[0], A4l[1], A4l[2], A4l[3],
                             B4h[2 * d], B4h[2 * d + 1]);
                    mma16816(acc[q][jn], A4h[0], A4h[1], A4h[2], A4h[3],
                             B4l[2 * d], B4l[2 * d + 1]);
                }
            }
        }
        __syncthreads();
    }

    const int r0 = m0 + w * 16 + gid;
    // q (scaled 1/32) and k: [token][32] layout
    #pragma unroll
    for (int q = 0; q < 2; q++) {
        unsigned* __restrict__ OH = q ? g_kh : g_qh;
        unsigned* __restrict__ OL = q ? g_kl : g_ql;
        const float sc = q ? 1.0f : 0.03125f;
        #pragma unroll
        for (int jn = 0; jn < 8; jn++) {
            float c0 = acc[q][jn][0] * sc, c1 = acc[q][jn][1] * sc;
            float c2 = acc[q][jn][2] * sc, c3 = acc[q][jn][3] * sc;
            int p = 4 * jn + tig;
            OH[(size_t)r0 * 32 + p]       = pack_hi(c0, c1);
            OL[(size_t)r0 * 32 + p]       = pack_rn(c0 - trunc_bf(c0), c1 - trunc_bf(c1));
            OH[(size_t)(r0 + 8) * 32 + p] = pack_hi(c2, c3);
            OL[(size_t)(r0 + 8) * 32 + p] = pack_rn(c2 - trunc_bf(c2), c3 - trunc_bf(c3));
        }
    }
    // v: [b][h][tp] layout.  lanes (gid, gid^1) hold adjacent token rows.
    {
        const int b0i = r0 >> 12;           // Tt = 4096
        const int t0i = r0 & 4095;
        const size_t vb = (size_t)b0i * 64 * 2048;
        #pragma unroll
        for (int jn = 0; jn < 8; jn++) {
            float c0 = acc[2][jn][0], c1 = acc[2][jn][1];
            float c2 = acc[2][jn][2], c3 = acc[2][jn][3];
            float d0 = __shfl_xor_sync(0xffffffffu, c0, 4);
            float d1 = __shfl_xor_sync(0xffffffffu, c1, 4);
            float d2 = __shfl_xor_sync(0xffffffffu, c2, 4);
            float d3 = __shfl_xor_sync(0xffffffffu, c3, 4);
            int p = 4 * jn + tig;
            size_t i0 = vb + (size_t)(2 * p) * 2048 + (t0i >> 1);
            size_t i1 = vb + (size_t)(2 * p) * 2048 + ((t0i + 8) >> 1);
            if (!(gid & 1)) {       // even token row: write h = 2p
                g_vh[i0] = pack_hi(c0, d0);
                g_vl[i0] = pack_rn(c0 - trunc_bf(c0), d0 - trunc_bf(d0));
                g_vh[i1] = pack_hi(c2, d2);
                g_vl[i1] = pack_rn(c2 - trunc_bf(c2), d2 - trunc_bf(d2));
            } else {                // odd token row: write h = 2p+1
                g_vh[i0 + 2048] = pack_hi(d1, c1);
                g_vl[i0 + 2048] = pack_rn(d1 - trunc_bf(d1), c1 - trunc_bf(c1));
                g_vh[i1 + 2048] = pack_hi(d3, c3);
                g_vl[i1 + 2048] = pack_rn(d3 - trunc_bf(d3), c3 - trunc_bf(c3));
            }
        }
    }
}

// ---------------------------------------------------------------------------
// Kernel 2: causal flash attention, split-KV 2-way, cp.async double-buffered,
// ldmatrix fragment loads.  K smem [token][h-pair] str 36; V smem [h][tp] str 36.
// ---------------------------------------------------------------------------
#define STG_U32 9216
#define ATTN_SMEM (2 * STG_U32 * 4)   // 73728 B

__global__ __launch_bounds__(128) void attn_kernel() {
    extern __shared__ unsigned smem[];

    const int b   = blockIdx.y;
    const int bx  = blockIdx.x;
    const int s   = bx & 1;
    const int qih = bx >> 1;
    const int qi  = (qih & 1) ? (63 - (qih >> 1)) : (qih >> 1);
    const int q0  = qi * 64;
    const int tid = threadIdx.x;
    const int w   = tid >> 5;
    const int lane = tid & 31;
    const int gid = lane >> 2;
    const int tig = lane & 3;

    const int half = (qi + 1) >> 1;
    const int kv0 = s ? half : 0;
    const int kv1 = s ? (qi + 1) : half;
    const int nt  = kv1 - kv0;

    float* __restrict__ op = g_op[s] + ((size_t)b * Tt + q0) * 64;

    if (nt == 0) {
        for (int i = tid; i < 64 * 64; i += 128) op[i] = 0.f;
        if (tid < 64) {
            g_m[s][(size_t)b * Tt + q0 + tid] = -1e30f;
            g_l[s][(size_t)b * Tt + q0 + tid] = 0.f;
        }
        return;
    }

    const unsigned* __restrict__ QH = g_qh + (size_t)b * Tt * 32;
    const unsigned* __restrict__ QL = g_ql + (size_t)b * Tt * 32;
    const unsigned* __restrict__ KH = g_kh + (size_t)b * Tt * 32;
    const unsigned* __restrict__ KL = g_kl + (size_t)b * Tt * 32;
    const unsigned* __restrict__ VH = g_vh + (size_t)b * 64 * 2048;
    const unsigned* __restrict__ VL = g_vl + (size_t)b * 64 * 2048;

    const unsigned smbase = (unsigned)__cvta_generic_to_shared(smem);

    // cp.async slot fields: rows kr+16i (0..63), 16B chunk kc (0..7)
    const int kr = tid >> 3, kc = tid & 7;

    #define PREFETCH(j) do {                                                    \
        const int kt__ = kv0 + (j);                                             \
        const unsigned bs__ = smbase + ((j) & 1) * (STG_U32 * 4);               \
        const int k0__ = kt__ * 64, kp__ = kt__ * 32;                           \
        _Pragma("unroll")                                                       \
        for (int i = 0; i < 4; i++) {                                           \
            int rr = kr + 16 * i;                                               \
            cpa16(bs__ + rr * 144 + kc * 16,          KH + (size_t)(k0__ + rr) * 32 + 4 * kc); \
            cpa16(bs__ + 9216 + rr * 144 + kc * 16,   KL + (size_t)(k0__ + rr) * 32 + 4 * kc); \
            cpa16(bs__ + 18432 + rr * 144 + kc * 16,  VH + (size_t)rr * 2048 + kp__ + 4 * kc); \
            cpa16(bs__ + 27648 + rr * 144 + kc * 16,  VL + (size_t)rr * 2048 + kp__ + 4 * kc); \
        }                                                                       \
        CP_COMMIT();                                                            \
    } while (0)

    // ldmatrix per-thread row offset (u32 units ×4 for bytes)
    const unsigned f_off = ((lane & 7) * 36 + (lane >> 3) * 4) * 4;

    unsigned qh[4][4], ql[4][4];
    {
        const int r0 = q0 + w * 16 + gid;
        #pragma unroll
        for (int c = 0; c < 4; c++) {
            qh[c][0] = QH[(size_t)r0 * 32 + 8 * c + tig];
            qh[c][1] = QH[(size_t)(r0 + 8) * 32 + 8 * c + tig];
            qh[c][2] = QH[(size_t)r0 * 32 + 8 * c + tig + 4];
            qh[c][3] = QH[(size_t)(r0 + 8) * 32 + 8 * c + tig + 4];
            ql[c][0] = QL[(size_t)r0 * 32 + 8 * c + tig];
            ql[c][1] = QL[(size_t)(r0 + 8) * 32 + 8 * c + tig];
            ql[c][2] = QL[(size_t)r0 * 32 + 8 * c + tig + 4];
            ql[c][3] = QL[(size_t)(r0 + 8) * 32 + 8 * c + tig + 4];
        }
    }

    PREFETCH(0);

    float o_acc[8][4];
    #pragma unroll
    for (int j = 0; j < 8; j++)
        #pragma unroll
        for (int e = 0; e < 4; e++) o_acc[j][e] = 0.f;
    float m0 = -1e30f, m1 = -1e30f;
    float l0 = 0.f, l1 = 0.f;

    for (int j = 0; j < nt; j++) {
        const int kt = kv0 + j;
        const int k0 = kt * 64;

        if (j + 1 < nt) { PREFETCH(j + 1); CP_WAIT(1); }
        else            { CP_WAIT(0); }
        __syncthreads();

        const unsigned stg = smbase + (j & 1) * (STG_U32 * 4);
        const unsigned kh_b = stg + f_off;
        const unsigned kl_b = stg + 9216 + f_off;
        const unsigned vh_b = stg + 18432 + f_off;
        const unsigned vl_b = stg + 27648 + f_off;

        // ---- S = Q K^T ----
        float sv[8][4];
        #pragma unroll
        for (int jn = 0; jn < 8; jn++) {
            sv[jn][0] = sv[jn][1] = sv[jn][2] = sv[jn][3] = 0.f;
            #pragma unroll
            for (int cc = 0; cc < 2; cc++) {
                unsigned B4h[4], B4l[4];
                ldsm4(B4h, kh_b + jn * 1152 + cc * 64);
                ldsm4(B4l, kl_b + jn * 1152 + cc * 64);
                #pragma unroll
                for (int d = 0; d < 2; d++) {
                    int c = 2 * cc + d;
                    mma16816(sv[jn], qh[c][0], qh[c][1], qh[c][2], qh[c][3],
                             B4h[2 * d], B4h[2 * d + 1]);
                    mma16816(sv[jn], ql[c][0], ql[c][1], ql[c][2], ql[c][3],
                             B4h[2 * d], B4h[2 * d + 1]);
                    mma16816(sv[jn], qh[c][0], qh[c][1], qh[c][2], qh[c][3],
                             B4l[2 * d], B4l[2 * d + 1]);
                }
            }
        }

        // ---- causal mask (diagonal tile only) ----
        if (kt == qi) {
            const int r0g = q0 + w * 16 + gid, r1g = r0g + 8;
            #pragma unroll
            for (int jn = 0; jn < 8; jn++) {
                int col = k0 + 8 * jn + 2 * tig;
                if (col     > r0g) sv[jn][0] = -1e30f;
                if (col + 1 > r0g) sv[jn][1] = -1e30f;
                if (col     > r1g) sv[jn][2] = -1e30f;
                if (col + 1 > r1g) sv[jn][3] = -1e30f;
            }
        }

        // ---- online softmax ----
        float tm0 = -1e30f, tm1 = -1e30f;
        #pragma unroll
        for (int jn = 0; jn < 8; jn++) {
            tm0 = fmaxf(tm0, fmaxf(sv[jn][0], sv[jn][1]));
            tm1 = fmaxf(tm1, fmaxf(sv[jn][2], sv[jn][3]));
        }
        tm0 = fmaxf(tm0, __shfl_xor_sync(0xffffffffu, tm0, 1));
        tm0 = fmaxf(tm0, __shfl_xor_sync(0xffffffffu, tm0, 2));
        tm1 = fmaxf(tm1, __shfl_xor_sync(0xffffffffu, tm1, 1));
        tm1 = fmaxf(tm1, __shfl_xor_sync(0xffffffffu, tm1, 2));

        float mn0 = fmaxf(m0, tm0), mn1 = fmaxf(m1, tm1);
        float al0 = __expf(m0 - mn0), al1 = __expf(m1 - mn1);
        m0 = mn0; m1 = mn1;

        float rs0 = 0.f, rs1 = 0.f;
        #pragma unroll
        for (int jn = 0; jn < 8; jn++) {
            sv[jn][0] = __expf(sv[jn][0] - mn0);
            sv[jn][1] = __expf(sv[jn][1] - mn0);
            sv[jn][2] = __expf(sv[jn][2] - mn1);
            sv[jn][3] = __expf(sv[jn][3] - mn1);
            rs0 += sv[jn][0] + sv[jn][1];
            rs1 += sv[jn][2] + sv[jn][3];
        }
        l0 = l0 * al0 + rs0;
        l1 = l1 * al1 + rs1;
        #pragma unroll
        for (int jn = 0; jn < 8; jn++) {
            o_acc[jn][0] *= al0; o_acc[jn][1] *= al0;
            o_acc[jn][2] *= al1; o_acc[jn][3] *= al1;
        }

        // ---- O += P V ----
        #pragma unroll
        for (int jpp = 0; jpp < 2; jpp++) {
            unsigned ph[2][4], pl[2][4];
            #pragma unroll
            for (int d = 0; d < 2; d++) {
                int jp = 2 * jpp + d;
                ph[d][0] = pack_hi(sv[2 * jp][0], sv[2 * jp][1]);
                ph[d][1] = pack_hi(sv[2 * jp][2], sv[2 * jp][3]);
                ph[d][2] = pack_hi(sv[2 * jp + 1][0], sv[2 * jp + 1][1]);
                ph[d][3] = pack_hi(sv[2 * jp + 1][2], sv[2 * jp + 1][3]);
                pl[d][0] = pack_rn(sv[2 * jp][0] - trunc_bf(sv[2 * jp][0]),
                                   sv[2 * jp][1] - trunc_bf(sv[2 * jp][1]));
                pl[d][1] = pack_rn(sv[2 * jp][2] - trunc_bf(sv[2 * jp][2]),
                                   sv[2 * jp][3] - trunc_bf(sv[2 * jp][3]));
                pl[d][2] = pack_rn(sv[2 * jp + 1][0] - trunc_bf(sv[2 * jp + 1][0]),
                                   sv[2 * jp + 1][1] - trunc_bf(sv[2 * jp + 1][1]));
                pl[d][3] = pack_rn(sv[2 * jp + 1][2] - trunc_bf(sv[2 * jp + 1][2]),
                                   sv[2 * jp + 1][3] - trunc_bf(sv[2 * jp + 1][3]));
            }
            #pragma unroll
            for (int jn = 0; jn < 8; jn++) {
                unsigned V4h[4], V4l[4];
                ldsm4(V4h, vh_b + jn * 1152 + jpp * 64);
                ldsm4(V4l, vl_b + jn * 1152 + jpp * 64);
                #pragma unroll
                for (int d = 0; d < 2; d++) {
                    mma16816(o_acc[jn], ph[d][0], ph[d][1], ph[d][2], ph[d][3],
                             V4h[2 * d], V4h[2 * d + 1]);
                    mma16816(o_acc[jn], pl[d][0], pl[d][1], pl[d][2], pl[d][3],
                             V4h[2 * d], V4h[2 * d + 1]);
                    mma16816(o_acc[jn], ph[d][0], ph[d][1], ph[d][2], ph[d][3],
                             V4l[2 * d], V4l[2 * d + 1]);
                }
            }
        }
        __syncthreads();
    }

    l0 += __shfl_xor_sync(0xffffffffu, l0, 1);
    l0 += __shfl_xor_sync(0xffffffffu, l0, 2);
    l1 += __shfl_xor_sync(0xffffffffu, l1, 1);
    l1 += __shfl_xor_sync(0xffffffffu, l1, 2);

    const int rloc = w * 16 + gid;
    if (tig == 0) {
        g_m[s][(size_t)b * Tt + q0 + rloc]     = m0;
        g_l[s][(size_t)b * Tt + q0 + rloc]     = l0;
        g_m[s][(size_t)b * Tt + q0 + rloc + 8] = m1;
        g_l[s][(size_t)b * Tt + q0 + rloc + 8] = l1;
    }
    #pragma unroll
    for (int jn = 0; jn < 8; jn++) {
        int n = 8 * jn + 2 * tig;
        *(float2*)&op[(size_t)rloc * 64 + n]       = make_float2(o_acc[jn][0], o_acc[jn][1]);
        *(float2*)&op[(size_t)(rloc + 8) * 64 + n] = make_float2(o_acc[jn][2], o_acc[jn][3]);
    }
}

// ---------------------------------------------------------------------------
// Kernel 3: combine the two KV splits.
// ---------------------------------------------------------------------------
__global__ __launch_bounds__(256) void combine_kernel(float* __restrict__ o) {
    int idx = blockIdx.x * 256 + threadIdx.x;
    int row = idx >> 6;
    float m0 = g_m[0][row], m1 = g_m[1][row];
    float l0 = g_l[0][row], l1 = g_l[1][row];
    float mx = fmaxf(m0, m1);
    float w0 = __expf(m0 - mx), w1 = __expf(m1 - mx);
    float inv = 1.0f / (w0 * l0 + w1 * l1);
    o[idx] = (w0 * g_op[0][idx] + w1 * g_op[1][idx]) * inv;
}

// ---------------------------------------------------------------------------
extern "C" void kernel_launch(void* const* d_in, const int* in_sizes, int n_in,
                              void* d_out, int out_size) {
    const float* x  = (const float*)d_in[0];
    const float* Wq = (const float*)d_in[1];
    const float* Wk = (const float*)d_in[2];
    const float* Wv = (const float*)d_in[3];
    float* out = (float*)d_out;

    qkv_gemm<<<dim3(BT / 64, 1), 128>>>(x, Wq, Wk, Wv);

    cudaFuncSetAttribute(attn_kernel,
                         cudaFuncAttributeMaxDynamicSharedMemorySize, ATTN_SMEM);
    attn_kernel<<<dim3(128, Bsz), 128, ATTN_SMEM>>>();

    combine_kernel<<<BT * 64 / 256, 256>>>(out);
}